// round 10
// baseline (speedup 1.0000x reference)
#include <cuda_runtime.h>
#include <cstddef>
#include <cstdint>

#define BB 512
#define TT 200
#define SI 100
#define DI 68
#define HS 256
#define HD 128
#define NN 10000
#define DDIM 512   // 2*HD + HS

typedef unsigned long long ull;

// packed f32x2 helpers (sm_103a FFMA2 — only reachable via PTX)
#define FFMA2(D, A, B, C) \
    asm("fma.rn.f32x2 %0, %1, %2, %3;" : "=l"(D) : "l"(A), "l"(B), "l"(C))
#define PACKDUP(D, S) \
    asm("mov.b64 %0, {%1, %1};" : "=l"(D) : "r"(__float_as_uint(S)))
#define UNPACK2(LO, HI, V) \
    asm("mov.b64 {%0, %1}, %2;" : "=f"(LO), "=f"(HI) : "l"(V))

// ---------------- scratch (static device arrays; no runtime allocation) ----------------
__device__ float g_xwf[BB * TT * HD];          // xw fwd (pre-activation input proj)
__device__ float g_xwb[BB * TT * HD];          // xw bwd
__device__ float g_dpf[BB * TT * 64];          // fwd routed-dot 2-col partials [seq][t][64]
__device__ float g_dpb[BB * TT * 64];          // bwd routed-dot 2-col partials
__device__ float g_cs[BB];                     // per-trial static dot + bias
__device__ float g_wdyn_t[DI * HD];            // w_dyn transposed [k][o]
__device__ float g_wihf_t[HD * HD];            // w_ih_f transposed [k][o]
__device__ float g_wihb_t[HD * HD];
__device__ float g_whhfp[64 * 256];            // Whh_f k-pair interleaved
__device__ float g_whhbp[64 * 256];
__device__ float g_ws1t[SI * HS];              // w_s1 transposed [i][j]
__device__ float g_ws2t[HS * HS];              // w_s2 transposed [i][j]
__device__ float g_bxf[HD];                    // b_ih_f + b_hh_f
__device__ float g_bxb[HD];

// ---------------- prep: transposes + k-pair packing + bias folds ----------------
__global__ void prep_kernel(const float* __restrict__ w_dyn,
                            const float* __restrict__ w_ih_f,
                            const float* __restrict__ w_hh_f,
                            const float* __restrict__ w_ih_b,
                            const float* __restrict__ w_hh_b,
                            const float* __restrict__ b_ih_f,
                            const float* __restrict__ b_hh_f,
                            const float* __restrict__ b_ih_b,
                            const float* __restrict__ b_hh_b,
                            const float* __restrict__ w_s1,
                            const float* __restrict__ w_s2) {
    int idx = blockIdx.x * blockDim.x + threadIdx.x;   // 65536 threads
    if (idx < HD * HD) {
        int o = idx / HD, k = idx % HD;
        g_wihf_t[k * HD + o] = w_ih_f[idx];
        g_wihb_t[k * HD + o] = w_ih_b[idx];
    }
    if (idx < 64 * HD) {               // Whh k-pair packed layout
        int j = idx >> 7, c = idx & 127;     // Wt[k][c] = w_hh[c*HD + k]
        g_whhfp[j * 256 + 2 * c]     = w_hh_f[c * HD + 2 * j];
        g_whhfp[j * 256 + 2 * c + 1] = w_hh_f[c * HD + 2 * j + 1];
        g_whhbp[j * 256 + 2 * c]     = w_hh_b[c * HD + 2 * j];
        g_whhbp[j * 256 + 2 * c + 1] = w_hh_b[c * HD + 2 * j + 1];
    }
    if (idx < HD * DI) {               // w_dyn is [HD,DI] row-major
        int o = idx / DI, i = idx % DI;
        g_wdyn_t[i * HD + o] = w_dyn[idx];
    }
    if (idx < HS * SI) {               // w_s1 is [HS,SI] row-major
        int o = idx / SI, i = idx % SI;
        g_ws1t[i * HS + o] = w_s1[idx];
    }
    if (idx < HS * HS) {               // w_s2 is [HS,HS] row-major
        int o = idx / HS, i = idx % HS;
        g_ws2t[i * HS + o] = w_s2[idx];
    }
    if (idx < HD) {
        g_bxf[idx] = b_ih_f[idx] + b_hh_f[idx];
        g_bxb[idx] = b_ih_b[idx] + b_hh_b[idx];
    }
}

// ---------------- static branch + fused cs: coalesced weight reads ----------------
__global__ void static_kernel(const float* __restrict__ xs,
                              const float* __restrict__ b1,
                              const float* __restrict__ b2,
                              const int* __restrict__ order,
                              const float* __restrict__ nw,
                              const float* __restrict__ nb) {
    int b = blockIdx.x;
    int j = threadIdx.x;                // 256 threads
    __shared__ float xsh[SI];
    __shared__ float s1[HS];
    __shared__ float partial[8];
    if (j < SI) xsh[j] = xs[b * SI + j];
    __syncthreads();
    float acc = b1[j];
    #pragma unroll 4
    for (int i = 0; i < SI; i++) acc += xsh[i] * g_ws1t[i * HS + j];   // coalesced
    s1[j] = fmaxf(acc, 0.f);
    __syncthreads();
    acc = b2[j];
    #pragma unroll 4
    for (int i = 0; i < HS; i++) acc += s1[i] * g_ws2t[i * HS + j];    // coalesced
    float sj = fmaxf(acc, 0.f);

    // fused cs: <s[b], Wn[:256]> + bn
    int n = order[b];
    float v = sj * nw[(size_t)n * DDIM + j];
    #pragma unroll
    for (int s = 16; s > 0; s >>= 1) v += __shfl_down_sync(0xffffffffu, v, s);
    if ((j & 31) == 0) partial[j >> 5] = v;
    __syncthreads();
    if (j == 0) {
        float sum = 0.f;
        #pragma unroll
        for (int i = 0; i < 8; i++) sum += partial[i];
        g_cs[b] = sum + nb[n];
    }
}

// ---------------- fused GEMM v2: 8 rows/warp, d pre-duplicated in smem ----------------
__global__ void __launch_bounds__(128, 4) fused_gemm_kernel(const float* __restrict__ xd,
                                                            const float* __restrict__ bdyn) {
    __shared__ float  xs[4][8 * DI];        // 8.7 KB: raw x rows
    __shared__ float2 dsd[4][8][HD];        // 32 KB: d duplicated pairs
    int w = threadIdx.x >> 5, lane = threadIdx.x & 31;
    size_t row0 = ((size_t)blockIdx.x * 4 + w) * 8;     // grid = 102400/32 = 3200

    const float* src = xd + row0 * DI;
    for (int i = lane; i < 8 * DI; i += 32) xs[w][i] = src[i];
    __syncwarp();

    // ---- stage 1: d tile, 8 rows x 4 cols (packed over col-pairs) ----
    {
        ulonglong2 bv = *(const ulonglong2*)&bdyn[4 * lane];
        ull ap[8], aq[8];
        #pragma unroll
        for (int r = 0; r < 8; r++) { ap[r] = bv.x; aq[r] = bv.y; }

        #pragma unroll 2
        for (int k = 0; k < DI; k += 4) {
            ulonglong2 w0 = *(const ulonglong2*)&g_wdyn_t[(k + 0) * HD + 4 * lane];
            ulonglong2 w1 = *(const ulonglong2*)&g_wdyn_t[(k + 1) * HD + 4 * lane];
            ulonglong2 w2 = *(const ulonglong2*)&g_wdyn_t[(k + 2) * HD + 4 * lane];
            ulonglong2 w3 = *(const ulonglong2*)&g_wdyn_t[(k + 3) * HD + 4 * lane];
            #pragma unroll
            for (int r = 0; r < 8; r++) {
                float4 x4 = *(const float4*)&xs[w][r * DI + k];
                ull p0, p1, p2, p3;
                PACKDUP(p0, x4.x); PACKDUP(p1, x4.y); PACKDUP(p2, x4.z); PACKDUP(p3, x4.w);
                FFMA2(ap[r], p0, w0.x, ap[r]); FFMA2(aq[r], p0, w0.y, aq[r]);
                FFMA2(ap[r], p1, w1.x, ap[r]); FFMA2(aq[r], p1, w1.y, aq[r]);
                FFMA2(ap[r], p2, w2.x, ap[r]); FFMA2(aq[r], p2, w2.y, aq[r]);
                FFMA2(ap[r], p3, w3.x, ap[r]); FFMA2(aq[r], p3, w3.y, aq[r]);
            }
        }
        // relu + store duplicated pairs: dsd[w][r][col] = (v, v)
        #pragma unroll
        for (int r = 0; r < 8; r++) {
            float lo, hi;
            UNPACK2(lo, hi, ap[r]);
            float v0 = fmaxf(lo, 0.f), v1 = fmaxf(hi, 0.f);
            UNPACK2(lo, hi, aq[r]);
            float v2 = fmaxf(lo, 0.f), v3 = fmaxf(hi, 0.f);
            dsd[w][r][4 * lane + 0] = make_float2(v0, v0);
            dsd[w][r][4 * lane + 1] = make_float2(v1, v1);
            dsd[w][r][4 * lane + 2] = make_float2(v2, v2);
            dsd[w][r][4 * lane + 3] = make_float2(v3, v3);
        }
    }
    __syncwarp();

    // ---- stage 2: dual GEMM over k=128, 8 rows (no PACKDUP) ----
    ulonglong2 bf2 = *(const ulonglong2*)&g_bxf[4 * lane];
    ulonglong2 bb2 = *(const ulonglong2*)&g_bxb[4 * lane];
    ull fp[8], fq[8], gp[8], gq[8];
    #pragma unroll
    for (int r = 0; r < 8; r++) { fp[r] = bf2.x; fq[r] = bf2.y; gp[r] = bb2.x; gq[r] = bb2.y; }

    #pragma unroll 2
    for (int k = 0; k < HD; k++) {
        ulonglong2 wf = *(const ulonglong2*)&g_wihf_t[k * HD + 4 * lane];
        ulonglong2 wb = *(const ulonglong2*)&g_wihb_t[k * HD + 4 * lane];
        #pragma unroll
        for (int r = 0; r < 8; r++) {
            ull d2 = *(const ull*)&dsd[w][r][k];      // broadcast LDS.64, already (v,v)
            FFMA2(fp[r], d2, wf.x, fp[r]);
            FFMA2(fq[r], d2, wf.y, fq[r]);
            FFMA2(gp[r], d2, wb.x, gp[r]);
            FFMA2(gq[r], d2, wb.y, gq[r]);
        }
    }

    size_t obase = row0 * HD + 4 * lane;
    #pragma unroll
    for (int r = 0; r < 8; r++) {
        *(ulonglong2*)&g_xwf[obase + (size_t)r * HD] = make_ulonglong2(fp[r], fq[r]);
        *(ulonglong2*)&g_xwb[obase + (size_t)r * HD] = make_ulonglong2(gp[r], gq[r]);
    }
}

// ---------------- RNN scan v6: ONE block barrier/step, warp-private h ----------------
// grid = 256 blocks, 2/SM. Block: dir = b&1, trials (b>>1)*4..+3. 8 warps.
// pass1 (unchanged): warp w holds W k-pairs [8w,8w+8) in regs; lane computes
//   cols 4l..4l+3 partials for 4 trials -> part[p][w] (trial stride 144: pad).
// pass2: warp w reduces cols [16w,16w+16) x 4 trials (lane: tr=l>>3,
//   colpair=16w+2(l&7)) — exactly the h-slice warp w reads next pass1, so the
//   second barrier collapses to __syncwarp. part double-buffered: the single
//   BAR after pass1 orders everything (all warps pass BAR_{s+1} only after
//   their pass2 of s, so part[p] reuse at s+2 is safe).
// Routed dot: per-thread 2-col partial -> straight to global (no shuffles on
//   the chain); combine kernel reduces the 64 partials per (seq,t).
__global__ void __launch_bounds__(256, 2) rnn_scan_kernel(const int* __restrict__ order,
                                                          const float* __restrict__ nw) {
    __shared__ float h_sm[4][HD];               // 2 KB
    __shared__ float part[2][8][4][144];        // 36 KB (trial stride 144 = bank-perm)
    __shared__ float wn_sm[4][HD];              // 2 KB
    int tid = threadIdx.x;
    int w = tid >> 5, l = tid & 31;
    int dir = blockIdx.x & 1;
    int tbase = (blockIdx.x >> 1) * 4;
    const float* __restrict__ Wp = dir ? g_whhbp : g_whhfp;
    const float* __restrict__ xw = dir ? g_xwb : g_xwf;
    float* __restrict__ dp = dir ? g_dpb : g_dpf;

    // cache packed W tile: k-pairs 8w..8w+7, cols 4l..4l+3 (32 x f32x2 = 64 regs)
    ull Wa[8][4];
    #pragma unroll
    for (int jj = 0; jj < 8; jj++) {
        ulonglong2 p0 = *(const ulonglong2*)&Wp[(8 * w + jj) * 256 + 8 * l];
        ulonglong2 p1 = *(const ulonglong2*)&Wp[(8 * w + jj) * 256 + 8 * l + 4];
        Wa[jj][0] = p0.x; Wa[jj][1] = p0.y; Wa[jj][2] = p1.x; Wa[jj][3] = p1.y;
    }

    // load routed weights for 4 trials (2 floats per thread)
    {
        int tr0 = tid >> 6, c0 = (tid & 63) * 2;
        int n = order[tbase + tr0];
        const float* wsrc = nw + (size_t)n * DDIM + HS + dir * HD + c0;
        wn_sm[tr0][c0]     = wsrc[0];
        wn_sm[tr0][c0 + 1] = wsrc[1];
    }

    // zero h (512 floats, 2 per thread)
    *(float2*)&((float*)h_sm)[2 * tid] = make_float2(0.f, 0.f);

    // pass2 slot: warp w owns cols [16w,16w+16); lane -> (trial, col-pair)
    int tr = l >> 3;
    int col = 16 * w + 2 * (l & 7);
    const float* xw_tr = xw + (size_t)(tbase + tr) * TT * HD + col;
    float* dp_tr = dp + ((size_t)(tbase + tr) * TT) * 64 + (8 * w + (l & 7));

    __syncthreads();
    float2 wn2 = *(const float2*)&wn_sm[tr][col];

    int t0 = dir ? (TT - 1) : 0;
    int dt = dir ? -1 : 1;

    for (int step = 0; step < TT; ++step) {
        int t = t0 + dt * step;
        int p = step & 1;

        // prefetch xw for pass2 (latency hidden by pass1)
        float2 xv = *(const float2*)&xw_tr[(size_t)t * HD];

        // ---- pass 1: partial GEMV over this warp's k-slice, per trial ----
        #pragma unroll
        for (int tr2 = 0; tr2 < 4; tr2++) {
            ull a0 = 0, a1 = 0, a2 = 0, a3 = 0;
            #pragma unroll
            for (int q = 0; q < 4; q++) {
                ulonglong2 h4 = *(const ulonglong2*)&h_sm[tr2][w * 16 + 4 * q];  // broadcast
                FFMA2(a0, h4.x, Wa[2 * q][0], a0); FFMA2(a0, h4.y, Wa[2 * q + 1][0], a0);
                FFMA2(a1, h4.x, Wa[2 * q][1], a1); FFMA2(a1, h4.y, Wa[2 * q + 1][1], a1);
                FFMA2(a2, h4.x, Wa[2 * q][2], a2); FFMA2(a2, h4.y, Wa[2 * q + 1][2], a2);
                FFMA2(a3, h4.x, Wa[2 * q][3], a3); FFMA2(a3, h4.y, Wa[2 * q + 1][3], a3);
            }
            float lo0, hi0, lo1, hi1, lo2, hi2, lo3, hi3;
            UNPACK2(lo0, hi0, a0);
            UNPACK2(lo1, hi1, a1);
            UNPACK2(lo2, hi2, a2);
            UNPACK2(lo3, hi3, a3);
            *(float4*)&part[p][w][tr2][4 * l] =
                make_float4(lo0 + hi0, lo1 + hi1, lo2 + hi2, lo3 + hi3);
        }
        __syncthreads();   // the ONLY block barrier per step

        // ---- pass 2: reduce 8 k-slices for (tr, cols col..col+1) ----
        // bank-perm: float2 index = ww*288 + tr*72 + 8w + (l&7); 8tr+cp+8w mod 32
        // covers all 32 banks within the warp -> conflict-free LDS.64.
        float2 s = *(const float2*)&part[p][0][tr][col - 16 * w + 0];
        // NOTE: part[p][ww][tr] rows are 144 floats; cols within warp-w group are
        // globally indexed, so read at offset col (0..127) inside the 144-row:
        s = *(const float2*)&part[p][0][tr][col];
        #pragma unroll
        for (int ww = 1; ww < 8; ww++) {
            float2 q = *(const float2*)&part[p][ww][tr][col];
            s.x += q.x; s.y += q.y;
        }
        s.x = fmaxf(s.x + xv.x, 0.f);
        s.y = fmaxf(s.y + xv.y, 0.f);
        *(float2*)&h_sm[tr][col] = s;    // own-warp slice: only this warp reads it

        // routed-dot partial: straight to global, off the critical chain
        dp_tr[(size_t)t * 64] = s.x * wn2.x + s.y * wn2.y;

        __syncwarp();      // own h slice visible to own warp's next pass1
    }
}

// ---------------- combine: out[b,t] = relu(cs + sum of 64+64 partials) ----------------
// One warp per (b,t): coalesced LDG.64, width-32 shuffle reduce.
__global__ void combine_kernel(float* __restrict__ out) {
    int e = blockIdx.x * 8 + (threadIdx.x >> 5);   // element index (b*TT+t)
    int l = threadIdx.x & 31;
    float2 vf = *(const float2*)&g_dpf[(size_t)e * 64 + 2 * l];
    float2 vb = *(const float2*)&g_dpb[(size_t)e * 64 + 2 * l];
    float s = (vf.x + vf.y) + (vb.x + vb.y);
    #pragma unroll
    for (int off = 16; off > 0; off >>= 1)
        s += __shfl_down_sync(0xffffffffu, s, off);
    if (l == 0) out[e] = fmaxf(s + g_cs[e / TT], 0.f);
}

// ---------------- launch ----------------
extern "C" void kernel_launch(void* const* d_in, const int* in_sizes, int n_in,
                              void* d_out, int out_size) {
    const float* x_static  = (const float*)d_in[0];
    const float* x_dynamic = (const float*)d_in[1];
    const int*   order     = (const int*)  d_in[2];
    const float* w_s1      = (const float*)d_in[3];
    const float* b_s1      = (const float*)d_in[4];
    const float* w_s2      = (const float*)d_in[5];
    const float* b_s2      = (const float*)d_in[6];
    const float* w_dyn     = (const float*)d_in[7];
    const float* b_dyn     = (const float*)d_in[8];
    const float* w_ih_f    = (const float*)d_in[9];
    const float* w_hh_f    = (const float*)d_in[10];
    const float* b_ih_f    = (const float*)d_in[11];
    const float* b_hh_f    = (const float*)d_in[12];
    const float* w_ih_b    = (const float*)d_in[13];
    const float* w_hh_b    = (const float*)d_in[14];
    const float* b_ih_b    = (const float*)d_in[15];
    const float* b_hh_b    = (const float*)d_in[16];
    const float* nw        = (const float*)d_in[17];
    const float* nb        = (const float*)d_in[18];
    float* out = (float*)d_out;

    prep_kernel<<<256, 256>>>(w_dyn, w_ih_f, w_hh_f, w_ih_b, w_hh_b,
                              b_ih_f, b_hh_f, b_ih_b, b_hh_b, w_s1, w_s2);
    static_kernel<<<BB, 256>>>(x_static, b_s1, b_s2, order, nw, nb);
    fused_gemm_kernel<<<BB * TT / 32, 128>>>(x_dynamic, b_dyn);
    rnn_scan_kernel<<<256, 256>>>(order, nw);
    combine_kernel<<<BB * TT / 8, 256>>>(out);
}